// round 10
// baseline (speedup 1.0000x reference)
#include <cuda_runtime.h>
#include <cuda_fp16.h>
#include <math.h>
#include <stdint.h>

#define NN 4096
#define EPSV 1e-9f

// ---------------- device scratch (static, allocation-free) ----------------
__device__ float g_prev[NN * 256];
__device__ float g_Wh[NN * 256];
__device__ float g_part[4 * NN * 256];   // 4-way j-split partial propagate sums
__device__ float g_diag[NN];
__device__ float g_rinv[NN];             // 1 / ||Wh_i||
__device__ __half g_WhH[NN * 256];       // Wh fp16, swizzled chunks

// ---------------- asm helpers ----------------
__device__ __forceinline__ uint32_t smem_u32(const void* p) {
    return (uint32_t)__cvta_generic_to_shared((void*)p);
}
__device__ __forceinline__ void ldsm4(uint32_t* r, uint32_t addr) {
    asm volatile("ldmatrix.sync.aligned.m8n8.x4.shared.b16 {%0,%1,%2,%3}, [%4];"
                 : "=r"(r[0]), "=r"(r[1]), "=r"(r[2]), "=r"(r[3]) : "r"(addr));
}
__device__ __forceinline__ void ldsm4t(uint32_t* r, uint32_t addr) {
    asm volatile("ldmatrix.sync.aligned.m8n8.x4.trans.shared.b16 {%0,%1,%2,%3}, [%4];"
                 : "=r"(r[0]), "=r"(r[1]), "=r"(r[2]), "=r"(r[3]) : "r"(addr));
}
__device__ __forceinline__ void mma_f16(float* c, const uint32_t* a, uint32_t b0, uint32_t b1) {
    asm volatile("mma.sync.aligned.m16n8k16.row.col.f32.f16.f16.f32 "
                 "{%0,%1,%2,%3}, {%4,%5,%6,%7}, {%8,%9}, {%0,%1,%2,%3};"
                 : "+f"(c[0]), "+f"(c[1]), "+f"(c[2]), "+f"(c[3])
                 : "r"(a[0]), "r"(a[1]), "r"(a[2]), "r"(a[3]), "r"(b0), "r"(b1));
}
__device__ __forceinline__ void cp16(uint32_t dst, const void* src) {
    asm volatile("cp.async.cg.shared.global [%0], [%1], 16;" :: "r"(dst), "l"(src));
}
#define CP_COMMIT() asm volatile("cp.async.commit_group;" ::: "memory")

// ---------------- math helpers ----------------
__device__ __forceinline__ float softplusf(float z) {
    return (z > 15.f) ? z : __logf(1.f + __expf(z));
}
__device__ __forceinline__ float eluf(float x) { return x > 0.f ? x : expm1f(x); }

__device__ __forceinline__ void fma16(float (&p)[4][4], float4 a, float4 b) {
    p[0][0] += a.x * b.x; p[0][1] += a.x * b.y; p[0][2] += a.x * b.z; p[0][3] += a.x * b.w;
    p[1][0] += a.y * b.x; p[1][1] += a.y * b.y; p[1][2] += a.y * b.z; p[1][3] += a.y * b.w;
    p[2][0] += a.z * b.x; p[2][1] += a.z * b.y; p[2][2] += a.z * b.z; p[2][3] += a.z * b.w;
    p[3][0] += a.w * b.x; p[3][1] += a.w * b.y; p[3][2] += a.w * b.z; p[3][3] += a.w * b.w;
}

__device__ __forceinline__ uint32_t pack_h(float a, float b) {
    __half2 h = __floats2half2_rn(a, b);
    return *(uint32_t*)&h;
}

// ---------------- Wh fp32 -> swizzled fp16 global array ----------------
// chunk layout: elem16 offset = row*D + (c ^ (row&7))*8 + (k&7), c = k>>3.
template <int D>
__global__ void cvt_kernel(const float* __restrict__ src, __half* __restrict__ H) {
    int idx = blockIdx.x * 256 + threadIdx.x;   // NN*D/8 chunks
    int row = idx / (D / 8);
    int c = idx % (D / 8);
    const float* s = src + (size_t)row * D + c * 8;
    float4 v0 = __ldg((const float4*)s);
    float4 v1 = __ldg((const float4*)(s + 4));
    int dcn = c ^ (row & 7);
    size_t off = (size_t)row * D + dcn * 8;
    __half2 h0 = __floats2half2_rn(v0.x, v0.y), h1 = __floats2half2_rn(v0.z, v0.w);
    __half2 h2 = __floats2half2_rn(v1.x, v1.y), h3 = __floats2half2_rn(v1.z, v1.w);
    *(uint4*)(H + off) = make_uint4(*(uint32_t*)&h0, *(uint32_t*)&h1,
                                    *(uint32_t*)&h2, *(uint32_t*)&h3);
}

// ---------------- small kernels ----------------
__global__ void diag_kernel(const float* __restrict__ adj, float* __restrict__ dg) {
    int i = blockIdx.x * 256 + threadIdx.x;
    dg[i] = adj[(size_t)i * (NN + 1)];
}

__global__ __launch_bounds__(256)
void gemm_bias_kernel(const float* __restrict__ A, const float* __restrict__ W,
                      const float* __restrict__ bias, float* __restrict__ C,
                      int K, int do_elu) {
    __shared__ float sA[16][68];
    __shared__ float sB[16][68];
    const int tid = threadIdx.x;
    const int ty = tid >> 4, tx = tid & 15;
    const int i0 = blockIdx.x * 64, j0 = blockIdx.y * 64;
    const int mload = tid >> 4;
    const int kload = tid & 15;
    const int kload2 = tid >> 6;
    const int nload = tid & 63;

    float p[4][4];
#pragma unroll
    for (int u = 0; u < 4; u++)
#pragma unroll
        for (int v = 0; v < 4; v++) p[u][v] = 0.f;

    for (int kb = 0; kb < K; kb += 16) {
        __syncthreads();
#pragma unroll
        for (int r = 0; r < 4; r++)
            sA[kload][mload + 16 * r] = A[(size_t)(i0 + mload + 16 * r) * K + kb + kload];
#pragma unroll
        for (int r = 0; r < 4; r++)
            sB[kload2 + 4 * r][nload] = W[(size_t)(kb + kload2 + 4 * r) * 256 + j0 + nload];
        __syncthreads();
#pragma unroll
        for (int kk = 0; kk < 16; kk++) {
            float4 a = *(const float4*)&sA[kk][4 * ty];
            float4 b = *(const float4*)&sB[kk][4 * tx];
            fma16(p, a, b);
        }
    }
#pragma unroll
    for (int u = 0; u < 4; u++) {
#pragma unroll
        for (int v = 0; v < 4; v++) {
            float val = p[u][v] + __ldg(bias + j0 + 4 * tx + v);
            if (do_elu) val = eluf(val);
            C[(size_t)(i0 + 4 * ty + u) * 256 + j0 + 4 * tx + v] = val;
        }
    }
}

// layer 3: Wh64 = zero-pad(prev @ W3 + b3) to [N,64]
__global__ void wh16_kernel(const float* __restrict__ H, const float* __restrict__ W3,
                            const float* __restrict__ b3, float* __restrict__ Wh) {
    int idx = blockIdx.x * 256 + threadIdx.x;  // NN*64
    int i = idx >> 6, c = idx & 63;
    float s = 0.f;
    if (c < 16) {
        s = __ldg(b3 + c);
        const float* h = H + (size_t)i * 256;
#pragma unroll 8
        for (int k = 0; k < 256; k++) s += h[k] * __ldg(W3 + k * 16 + c);
    }
    Wh[idx] = s;
}

// outputs INVERSE row norm
__global__ void rownorm_kernel(const float* __restrict__ Wh, float* __restrict__ r, int D) {
    int row = blockIdx.x * 8 + (threadIdx.x >> 5);
    int lane = threadIdx.x & 31;
    float s = 0.f;
    for (int k = lane; k < D; k += 32) {
        float v = Wh[(size_t)row * D + k];
        s += v * v;
    }
#pragma unroll
    for (int o = 16; o; o >>= 1) s += __shfl_xor_sync(0xffffffffu, s, o);
    if (lane == 0) r[row] = 1.f / fmaxf(sqrtf(s), 1e-5f);
}

// ---------------- fused mma.sync attention layer (single fp16, BM=64) --------
// grid (64, 4): 64-row i tiles x 4-way j split; 128 threads, 4 warps over i.
// SMEM: Ah[64xD] fp16 + B double buffer (2 x 64xD fp16) + adj tile [64][64] f32
// (chunk-XOR swizzled). Sized for 2 CTAs/SM.
template <int D>  // 256, or 64 (layer 3 zero-padded)
__global__ __launch_bounds__(128)
void fused_mma(const __half* __restrict__ WhH,
               const float* __restrict__ rvec,
               const float* __restrict__ diagv, const float* __restrict__ adj,
               const float* __restrict__ dc, const float* __restrict__ cf,
               float* __restrict__ part) {
    constexpr int KCH = D / 16;   // score k-chunks
    constexpr int DNB = D / 8;    // propagate n-blocks (P accumulators)
    constexpr int ROWB = 2 * D;   // smem row bytes (fp16)
    constexpr int BBYTES = 64 * ROWB;

    extern __shared__ char sm[];
    char* Ah = sm;
    char* Bb = sm + 64 * ROWB;
    float* adjS = (float*)(sm + 64 * ROWB + 2 * BBYTES);
    const uint32_t ah_b = smem_u32(Ah);
    const uint32_t bb_b = smem_u32(Bb);
    const uint32_t adj_b = smem_u32(adjS);

    const int tid = threadIdx.x;
    const int w = tid >> 5, lane = tid & 31;  // 4 warps
    const int i0 = blockIdx.x * 64;
    const int jbase = blockIdx.y * (NN / 4);
    const int row0 = lane >> 2;
    const int qp = lane & 3;
    const int gi0 = i0 + w * 16 + row0;

    const int lrow = lane & 15;
    const int lsel = lane >> 4;
    const int lx7 = lane & 7;

    // per-layer scalars
    float dc0 = __ldg(dc), dc1 = __ldg(dc + 1);
    float f0 = __ldg(cf), f1 = __ldg(cf + 1), f2 = __ldg(cf + 2);
    float mxc = fmaxf(f0, fmaxf(f1, f2));
    float e0 = __expf(f0 - mxc), e1 = __expf(f1 - mxc), e2 = __expf(f2 - mxc);
    float inv = 1.f / (e0 + e1 + e2);
    float c0 = e0 * inv, c1 = e1 * inv;
    float ri0 = __ldg(rvec + gi0), ri8 = __ldg(rvec + gi0 + 8);   // inverse norms
    float di0 = __ldg(diagv + gi0), di8 = __ldg(diagv + gi0 + 8);

    // A tile: raw copy (swizzle preserved: i0 multiple of 64 keeps row mod 8)
    {
        const uint4* gH = (const uint4*)(WhH + (size_t)i0 * D);
        uint4* sH = (uint4*)Ah;
#pragma unroll 4
        for (int it = tid; it < 8 * D; it += 128) sH[it] = __ldg(gH + it);
    }

    // prefetch B tile 0 into buffer 0
    {
        const char* src = (const char*)(WhH + (size_t)jbase * D);
        for (int off = tid * 16; off < BBYTES; off += 2048) cp16(bb_b + off, src + off);
        CP_COMMIT();
    }

    float pacc[DNB][4];
#pragma unroll
    for (int q = 0; q < DNB; q++)
#pragma unroll
        for (int v = 0; v < 4; v++) pacc[q][v] = 0.f;

    const int arow = w * 16 + lrow;
    const int ra = w * 16 + row0;

    for (int tt = 0; tt < 16; tt++) {
        int j0 = jbase + tt * 64;
        __syncthreads();   // prop(tt-1) done reading B[(tt+1)&1] and adjS

        // adj[tt] tile prefetch: 64 rows x 64 cols f32, chunk-XOR swizzled
        {
            const char* asrc = (const char*)(adj + (size_t)i0 * NN + j0);
#pragma unroll
            for (int k = 0; k < 8; k++) {
                int idx = tid + k * 128;
                int row = idx >> 4, ch = idx & 15;
                cp16(adj_b + row * 256 + ((ch ^ (row & 7)) << 4),
                     asrc + (size_t)row * (NN * 4) + ch * 16);
            }
            CP_COMMIT();
        }
        if (tt + 1 < 16) {   // B[tt+1] prefetch
            const char* src = (const char*)(WhH + (size_t)(j0 + 64) * D);
            uint32_t dst = bb_b + ((tt + 1) & 1) * BBYTES;
            for (int off = tid * 16; off < BBYTES; off += 2048) cp16(dst + off, src + off);
            CP_COMMIT();
            asm volatile("cp.async.wait_group 2;" ::: "memory");  // B[tt] done
        } else {
            asm volatile("cp.async.wait_group 1;" ::: "memory");  // B[tt] done
        }
        __syncthreads();
        const uint32_t bcur = bb_b + (tt & 1) * BBYTES;

        // ---- score: S[16x64] per warp, single fp16 ----
        float sacc[8][4];
#pragma unroll
        for (int q = 0; q < 8; q++)
#pragma unroll
            for (int v = 0; v < 4; v++) sacc[q][v] = 0.f;

#pragma unroll
        for (int kc = 0; kc < KCH; kc++) {
            uint32_t achunk = (uint32_t)(((kc * 2 + lsel) ^ lx7) * 16);
            uint32_t ah[4];
            ldsm4(ah, ah_b + (uint32_t)arow * ROWB + achunk);
#pragma unroll
            for (int nh = 0; nh < 2; nh++) {
#pragma unroll
                for (int t = 0; t < 2; t++) {
                    int n00 = nh * 32 + t * 16;
                    uint32_t brow = (uint32_t)(n00 + lrow);
                    uint32_t boff = brow * ROWB + (uint32_t)(((kc * 2 + lsel) ^ (brow & 7)) * 16);
                    uint32_t bh[4];
                    ldsm4(bh, bcur + boff);
                    int nb = nh * 4 + t * 2;
                    mma_f16(sacc[nb],     ah, bh[0], bh[2]);
                    mma_f16(sacc[nb + 1], ah, bh[1], bh[3]);
                }
            }
        }

        // adj[tt] now needed
        if (tt + 1 < 16) {
            asm volatile("cp.async.wait_group 1;" ::: "memory");
        } else {
            asm volatile("cp.async.wait_group 0;" ::: "memory");
        }
        __syncthreads();

        // ---- weight epilogue: S -> w (fp16 A-fragments, in regs) ----
        uint32_t wh[4][4];
#pragma unroll
        for (int nb = 0; nb < 8; nb++) {
            int jp = j0 + nb * 8 + 2 * qp;
            int colc = nb * 8 + 2 * qp;
            int chunk = colc >> 2, within = colc & 3;
            int swo = ((chunk ^ (ra & 7)) << 2) + within;
            float2 a0 = *(const float2*)(adjS + ra * 64 + swo);
            float2 a8 = *(const float2*)(adjS + (ra + 8) * 64 + swo);
            float2 rj = __ldg((const float2*)(rvec + jp));   // inverse norms

            float ww[4];
            float sv[4] = {sacc[nb][0], sacc[nb][1], sacc[nb][2], sacc[nb][3]};
            float av[4] = {a0.x, a0.y, a8.x, a8.y};
            float rv[4] = {rj.x, rj.y, rj.x, rj.y};
            float riv[4] = {ri0, ri0, ri8, ri8};
            float div_[4] = {di0, di0, di8, di8};
            int giv[4] = {gi0, gi0, gi0 + 8, gi0 + 8};
            int gjv[4] = {jp, jp + 1, jp, jp + 1};
#pragma unroll
            for (int u = 0; u < 4; u++) {
                float a = av[u];
                float am = fmaxf(a, EPSV);
                float z = dc0 * (div_[u] * __frcp_rn(am) - 1.f) + dc1;
                float sp = softplusf(z);
                float e = sv[u] * riv[u] * rv[u];
                float att = e * a * sp;
                if (giv[u] == gjv[u]) att = 0.f;
                ww[u] = (att > 0.f ? c0 : c1) * att;
            }
            int kc = nb >> 1, o = (nb & 1) * 2;
            wh[kc][o] = pack_h(ww[0], ww[1]);
            wh[kc][o + 1] = pack_h(ww[2], ww[3]);
        }

        // ---- propagate: P += w @ Whj (B via ldmatrix.trans), single fp16 ----
#pragma unroll
        for (int kc = 0; kc < 4; kc++) {
            uint32_t jrow = (uint32_t)(kc * 16 + lrow);
#pragma unroll
            for (int dt = 0; dt < D / 16; dt++) {
                uint32_t boff = jrow * ROWB + (uint32_t)(((dt * 2 + lsel) ^ (jrow & 7)) * 16);
                uint32_t bh[4];
                ldsm4t(bh, bcur + boff);
                int p0 = dt * 2, p1 = dt * 2 + 1;
                mma_f16(pacc[p0], wh[kc], bh[0], bh[1]);
                mma_f16(pacc[p1], wh[kc], bh[2], bh[3]);
            }
        }
    }

    // ---- writeout ----
    float* dst0 = part + ((size_t)blockIdx.y * NN + gi0) * D;
    float* dst8 = dst0 + 8 * (size_t)D;
#pragma unroll
    for (int q = 0; q < DNB; q++) {
        int d = q * 8 + 2 * qp;
        *(float2*)(dst0 + d) = make_float2(pacc[q][0], pacc[q][1]);
        *(float2*)(dst8 + d) = make_float2(pacc[q][2], pacc[q][3]);
    }
}

// ---------------- epilogue layers 0..2 ----------------
__global__ void epi_kernel(const float* __restrict__ part, const float* __restrict__ Wh,
                           float* __restrict__ prev,
                           const float* __restrict__ cf, const float* __restrict__ sp,
                           float coeff) {
    int idx = blockIdx.x * 256 + threadIdx.x;
    float f0 = __ldg(cf), f1 = __ldg(cf + 1), f2 = __ldg(cf + 2);
    float mxc = fmaxf(f0, fmaxf(f1, f2));
    float e0 = __expf(f0 - mxc), e1 = __expf(f1 - mxc), e2 = __expf(f2 - mxc);
    float c2 = e2 / (e0 + e1 + e2);
    float s = softplusf(__ldg(sp));
    const size_t ST = (size_t)NN * 256;
    float psum = part[idx] + part[ST + idx] + part[2 * ST + idx] + part[3 * ST + idx];
    float inner = s * (psum + c2 * Wh[idx]);
    prev[idx] += coeff * eluf(inner);
}

// ---------------- final: log_softmax over 16 classes (part stride 64) --------
__global__ void final_kernel(const float* __restrict__ part, const float* __restrict__ Wh,
                             const float* __restrict__ cf, const float* __restrict__ sp,
                             float* __restrict__ out) {
    int row = blockIdx.x * blockDim.x + threadIdx.x;
    float f0 = __ldg(cf), f1 = __ldg(cf + 1), f2 = __ldg(cf + 2);
    float mxc = fmaxf(f0, fmaxf(f1, f2));
    float e0 = __expf(f0 - mxc), e1 = __expf(f1 - mxc), e2 = __expf(f2 - mxc);
    float c2 = e2 / (e0 + e1 + e2);
    float s = softplusf(__ldg(sp));
    const size_t ST = (size_t)NN * 64;

    float v[16];
    float mx = -3.4e38f;
#pragma unroll
    for (int c = 0; c < 16; c++) {
        size_t o = (size_t)row * 64 + c;
        float psum = part[o] + part[ST + o] + part[2 * ST + o] + part[3 * ST + o];
        float t = s * (psum + c2 * Wh[(size_t)row * 64 + c]);
        v[c] = t;
        mx = fmaxf(mx, t);
    }
    float lse = 0.f;
#pragma unroll
    for (int c = 0; c < 16; c++) lse += expf(v[c] - mx);
    lse = logf(lse);
#pragma unroll
    for (int c = 0; c < 16; c++) out[row * 16 + c] = v[c] - mx - lse;
}

// ---------------- host launcher ----------------
extern "C" void kernel_launch(void* const* d_in, const int* in_sizes, int n_in,
                              void* d_out, int out_size) {
    const float* x   = (const float*)d_in[0];
    const float* adj = (const float*)d_in[1];
    const float* Wf  = (const float*)d_in[2];
    const float* bf  = (const float*)d_in[3];
    const float* W0  = (const float*)d_in[4];
    const float* b0  = (const float*)d_in[5];
    const float* W1  = (const float*)d_in[6];
    const float* b1  = (const float*)d_in[7];
    const float* W2  = (const float*)d_in[8];
    const float* b2  = (const float*)d_in[9];
    const float* W3  = (const float*)d_in[10];
    const float* b3  = (const float*)d_in[11];
    const float* dcs = (const float*)d_in[12];
    const float* cfs = (const float*)d_in[13];
    const float* sps = (const float*)d_in[14];
    float* out = (float*)d_out;

    float *p_prev, *p_Wh, *p_part, *p_diag, *p_r;
    __half *p_WhH;
    cudaGetSymbolAddress((void**)&p_prev, g_prev);
    cudaGetSymbolAddress((void**)&p_Wh, g_Wh);
    cudaGetSymbolAddress((void**)&p_part, g_part);
    cudaGetSymbolAddress((void**)&p_diag, g_diag);
    cudaGetSymbolAddress((void**)&p_r, g_rinv);
    cudaGetSymbolAddress((void**)&p_WhH, g_WhH);

    // smem: A(64xD) + 2xB(64xD) + adj 16KB swizzled
    const int SM256 = 64 * 512 + 2 * 32768 + 16384;  // 114688 -> 2 CTAs/SM
    const int SM64  = 64 * 128 + 2 * 8192 + 16384;   //  40960
    cudaFuncSetAttribute(fused_mma<256>, cudaFuncAttributeMaxDynamicSharedMemorySize, SM256);
    cudaFuncSetAttribute(fused_mma<64>,  cudaFuncAttributeMaxDynamicSharedMemorySize, SM64);

    const float cI1 = 1.0f;
    const float cI2 = logf(1.0f / 27.0f + 1.0f);
    const float cI3 = logf(1.0f / 64.0f + 1.0f);

    diag_kernel<<<NN / 256, 256>>>(adj, p_diag);
    gemm_bias_kernel<<<dim3(64, 4), 256>>>(x, Wf, bf, p_prev, 512, 1);

    // ---- layer 0 ----
    gemm_bias_kernel<<<dim3(64, 4), 256>>>(x, W0, b0, p_Wh, 512, 0);
    rownorm_kernel<<<512, 256>>>(p_Wh, p_r, 256);
    cvt_kernel<256><<<512, 256>>>(p_Wh, p_WhH);
    fused_mma<256><<<dim3(64, 4), 128, SM256>>>(p_WhH, p_r, p_diag, adj,
                                                dcs + 0, cfs + 0, p_part);
    epi_kernel<<<NN, 256>>>(p_part, p_Wh, p_prev, cfs + 0, sps + 0, cI1);

    // ---- layer 1 ----
    gemm_bias_kernel<<<dim3(64, 4), 256>>>(p_prev, W1, b1, p_Wh, 256, 0);
    rownorm_kernel<<<512, 256>>>(p_Wh, p_r, 256);
    cvt_kernel<256><<<512, 256>>>(p_Wh, p_WhH);
    fused_mma<256><<<dim3(64, 4), 128, SM256>>>(p_WhH, p_r, p_diag, adj,
                                                dcs + 2, cfs + 3, p_part);
    epi_kernel<<<NN, 256>>>(p_part, p_Wh, p_prev, cfs + 3, sps + 1, cI2);

    // ---- layer 2 ----
    gemm_bias_kernel<<<dim3(64, 4), 256>>>(p_prev, W2, b2, p_Wh, 256, 0);
    rownorm_kernel<<<512, 256>>>(p_Wh, p_r, 256);
    cvt_kernel<256><<<512, 256>>>(p_Wh, p_WhH);
    fused_mma<256><<<dim3(64, 4), 128, SM256>>>(p_WhH, p_r, p_diag, adj,
                                                dcs + 4, cfs + 6, p_part);
    epi_kernel<<<NN, 256>>>(p_part, p_Wh, p_prev, cfs + 6, sps + 2, cI3);

    // ---- layer 3 (D=16 zero-padded to 64) ----
    wh16_kernel<<<NN * 64 / 256, 256>>>(p_prev, W3, b3, p_Wh);
    rownorm_kernel<<<512, 256>>>(p_Wh, p_r, 64);
    cvt_kernel<64><<<128, 256>>>(p_Wh, p_WhH);
    fused_mma<64><<<dim3(64, 4), 128, SM64>>>(p_WhH, p_r, p_diag, adj,
                                              dcs + 6, cfs + 9, p_part);
    final_kernel<<<NN / 256, 256>>>(p_part, p_Wh, cfs + 9, sps + 3, out);
}